// round 3
// baseline (speedup 1.0000x reference)
#include <cuda_runtime.h>

#define NN 100000
#define NE 3200000
#define FIN 128
#define FOUT 16
#define SCAN_BS 512
#define SCAN_NBLK ((NN + SCAN_BS - 1) / SCAN_BS)   // 196

// Static scratch (no allocations allowed)
__device__ float g_deg[NN];                  // weighted degree -> dinv in place
__device__ float g_hs[(size_t)NN * FOUT];    // (x@W) * dinv[row]
__device__ int   g_cnt[NN];                  // in-degree counts (int)
__device__ int   g_off[NN + 1];              // CSR offsets
__device__ int   g_bsum[SCAN_NBLK];          // scan block sums
__device__ int   g_row32[NE];
__device__ int   g_col32[NE];
__device__ int   g_rank[NE];                 // slot within destination bucket
__device__ uint2 g_packed[NE];               // (row, weight) sorted by destination
__device__ int   g_is64;

// ---- dtype probe: int64 little-endian with ids < 2^31 has zero odd words ----
__global__ void k_detect(const unsigned int* __restrict__ ei32) {
    if (threadIdx.x == 0 && blockIdx.x == 0) {
        int all_zero = 1;
        for (int k = 0; k < 64; k++)
            if (ei32[2 * k + 1] != 0u) { all_zero = 0; break; }
        g_is64 = all_zero;
    }
}

__device__ __forceinline__ int load_idx(const void* ei, long long p64, int p32, int is64) {
    if (is64) return (int)((const long long*)ei)[p64];
    return ((const int*)ei)[p32];
}

__global__ void k_init() {
    int i = blockIdx.x * blockDim.x + threadIdx.x;
    if (i < NN) { g_deg[i] = 1.0f; g_cnt[i] = 0; }
}

// read edges once: convert to int32, rank within dest bucket, weighted degree
__global__ void k_pass1(const void* __restrict__ ei, const float* __restrict__ ew) {
    int e = blockIdx.x * blockDim.x + threadIdx.x;
    if (e >= NE) return;
    int is64 = g_is64;
    int r = load_idx(ei, e, e, is64);
    int c = load_idx(ei, (long long)NE + e, NE + e, is64);
    g_row32[e] = r;
    g_col32[e] = c;
    g_rank[e] = atomicAdd(&g_cnt[c], 1);
    atomicAdd(&g_deg[c], ew[e]);
}

__global__ void k_dinv() {
    int i = blockIdx.x * blockDim.x + threadIdx.x;
    if (i < NN) g_deg[i] = rsqrtf(g_deg[i]);  // deg >= 1 (self-loop)
}

// ---- exclusive scan of g_cnt -> g_off ----
__global__ void k_scan1() {  // grid SCAN_NBLK, block SCAN_BS
    __shared__ int s[SCAN_BS];
    int gid = blockIdx.x * SCAN_BS + threadIdx.x;
    int v = (gid < NN) ? g_cnt[gid] : 0;
    s[threadIdx.x] = v;
    __syncthreads();
#pragma unroll
    for (int d = 1; d < SCAN_BS; d <<= 1) {
        int t = (threadIdx.x >= d) ? s[threadIdx.x - d] : 0;
        __syncthreads();
        s[threadIdx.x] += t;
        __syncthreads();
    }
    if (gid < NN) g_off[gid] = s[threadIdx.x] - v;        // exclusive (local)
    if (threadIdx.x == SCAN_BS - 1) g_bsum[blockIdx.x] = s[threadIdx.x];
}

__global__ void k_scan2() {  // 1 thread, 196 values
    if (threadIdx.x == 0 && blockIdx.x == 0) {
        int acc = 0;
        for (int i = 0; i < SCAN_NBLK; i++) {
            int t = g_bsum[i];
            g_bsum[i] = acc;
            acc += t;
        }
    }
}

__global__ void k_scan3() {
    int gid = blockIdx.x * SCAN_BS + threadIdx.x;
    if (gid < NN) g_off[gid] += g_bsum[blockIdx.x];
    if (gid == 0) g_off[NN] = NE;  // total edge count is fixed
}

// place each edge at its CSR slot: plain 8B stores, no atomics
__global__ void k_build(const float* __restrict__ ew) {
    int e = blockIdx.x * blockDim.x + threadIdx.x;
    if (e >= NE) return;
    int c = g_col32[e];
    int pos = g_off[c] + g_rank[e];
    g_packed[pos] = make_uint2((unsigned)g_row32[e], __float_as_uint(ew[e]));
}

// hs[node] = (x[node] @ W) * dinv[node]
__global__ void __launch_bounds__(256) k_gemm(const float* __restrict__ x,
                                              const float* __restrict__ W) {
    __shared__ float4 Ws[FIN * FOUT / 4];  // [k][f] layout, 8KB
    for (int i = threadIdx.x; i < FIN * FOUT / 4; i += 256)
        Ws[i] = ((const float4*)W)[i];
    __syncthreads();

    int node = blockIdx.x * 256 + threadIdx.x;
    if (node >= NN) return;

    const float4* xr = (const float4*)(x + (size_t)node * FIN);
    float acc[FOUT];
#pragma unroll
    for (int f = 0; f < FOUT; f++) acc[f] = 0.0f;

#pragma unroll 4
    for (int k4 = 0; k4 < FIN / 4; k4++) {
        float4 xv = xr[k4];
#pragma unroll
        for (int j = 0; j < 4; j++) {
            float xs = (j == 0) ? xv.x : (j == 1) ? xv.y : (j == 2) ? xv.z : xv.w;
            int k = k4 * 4 + j;
#pragma unroll
            for (int q = 0; q < 4; q++) {
                float4 w = Ws[k * 4 + q];
                acc[q * 4 + 0] += xs * w.x;
                acc[q * 4 + 1] += xs * w.y;
                acc[q * 4 + 2] += xs * w.z;
                acc[q * 4 + 3] += xs * w.w;
            }
        }
    }

    float di = g_deg[node];  // holds dinv now
    float4* hs4 = (float4*)(g_hs + (size_t)node * FOUT);
#pragma unroll
    for (int q = 0; q < 4; q++)
        hs4[q] = make_float4(acc[q * 4 + 0] * di, acc[q * 4 + 1] * di,
                             acc[q * 4 + 2] * di, acc[q * 4 + 3] * di);
}

// gather aggregation: 16 lanes per node, lane f owns output feature f.
// out[c][f] = (hs[c][f] + sum_edges w * hs[r][f]) * dinv[c] + b[f]
__global__ void __launch_bounds__(256) k_agg(float* __restrict__ out,
                                             const float* __restrict__ b) {
    int tid = threadIdx.x;
    int lane16 = tid & 15;
    int node = blockIdx.x * 16 + (tid >> 4);
    if (node >= NN) return;

    int beg = g_off[node];
    int end = g_off[node + 1];
    float acc = 0.0f;
    for (int p = beg; p < end; p++) {
        uint2 pk = g_packed[p];                 // same addr across 16 lanes -> broadcast
        float w = __uint_as_float(pk.y);
        acc += w * g_hs[(size_t)pk.x * FOUT + lane16];  // coalesced 64B row
    }
    float di = g_deg[node];
    out[(size_t)node * FOUT + lane16] =
        (acc + g_hs[(size_t)node * FOUT + lane16]) * di + b[lane16];
}

extern "C" void kernel_launch(void* const* d_in, const int* in_sizes, int n_in,
                              void* d_out, int out_size) {
    const float* x = (const float*)d_in[0];
    const void* ei = d_in[1];
    const float* ew = (const float*)d_in[2];
    const float* W = (const float*)d_in[3];
    const float* b = (const float*)d_in[4];
    float* out = (float*)d_out;

    k_detect<<<1, 32>>>((const unsigned int*)ei);
    k_init<<<(NN + 255) / 256, 256>>>();
    k_pass1<<<(NE + 255) / 256, 256>>>(ei, ew);
    k_dinv<<<(NN + 255) / 256, 256>>>();
    k_scan1<<<SCAN_NBLK, SCAN_BS>>>();
    k_scan2<<<1, 32>>>();
    k_scan3<<<SCAN_NBLK, SCAN_BS>>>();
    k_build<<<(NE + 255) / 256, 256>>>(ew);
    k_gemm<<<(NN + 255) / 256, 256>>>(x, W);
    k_agg<<<(NN + 15) / 16, 256>>>(out, b);
}

// round 4
// speedup vs baseline: 1.1331x; 1.1331x over previous
#include <cuda_runtime.h>

#define NN 100000
#define NE 3200000
#define FIN 128
#define FOUT 16
#define SCAN_BS 512
#define SCAN_NBLK ((NN + SCAN_BS - 1) / SCAN_BS)   // 196

// Static scratch
__device__ float g_deg[NN];                  // dinv
__device__ float g_hs[(size_t)NN * FOUT];    // (x@W) * dinv[row]
__device__ int   g_cnt[NN];                  // in-degree counts
__device__ int   g_off[NN + 1];              // CSR offsets
__device__ int   g_bsum[SCAN_NBLK];
__device__ int   g_row32[NE];
__device__ int   g_col32[NE];
__device__ int   g_rank[NE];
__device__ uint2 g_packed[NE];               // (row, weight) grouped by destination
__device__ int   g_is64;

// probe dtype (int64 little-endian with ids < 2^31 has zero odd 32-bit words) + zero counts
__global__ void k_init(const unsigned int* __restrict__ ei32) {
    int i = blockIdx.x * blockDim.x + threadIdx.x;
    if (i < NN) g_cnt[i] = 0;
    if (i == 0) {
        int all_zero = 1;
        for (int k = 0; k < 64; k++)
            if (ei32[2 * k + 1] != 0u) { all_zero = 0; break; }
        g_is64 = all_zero;
    }
}

// 2 edges per thread: convert indices, rank via single atomic per edge
__global__ void k_pass1(const void* __restrict__ ei, const float* __restrict__ ew) {
    int t = blockIdx.x * blockDim.x + threadIdx.x;
    if (t >= NE / 2) return;
    int r0, r1, c0, c1;
    if (g_is64) {
        const longlong2* rows = (const longlong2*)ei;
        const longlong2* cols = (const longlong2*)((const long long*)ei + NE);
        longlong2 rv = rows[t], cv = cols[t];
        r0 = (int)rv.x; r1 = (int)rv.y; c0 = (int)cv.x; c1 = (int)cv.y;
    } else {
        const int2* rows = (const int2*)ei;
        const int2* cols = (const int2*)((const int*)ei + NE);
        int2 rv = rows[t], cv = cols[t];
        r0 = rv.x; r1 = rv.y; c0 = cv.x; c1 = cv.y;
    }
    ((int2*)g_row32)[t] = make_int2(r0, r1);
    ((int2*)g_col32)[t] = make_int2(c0, c1);
    int k0 = atomicAdd(&g_cnt[c0], 1);
    int k1 = atomicAdd(&g_cnt[c1], 1);
    ((int2*)g_rank)[t] = make_int2(k0, k1);
}

// block-local exclusive scan
__global__ void k_scan1() {
    __shared__ int s[SCAN_BS];
    int gid = blockIdx.x * SCAN_BS + threadIdx.x;
    int v = (gid < NN) ? g_cnt[gid] : 0;
    s[threadIdx.x] = v;
    __syncthreads();
#pragma unroll
    for (int d = 1; d < SCAN_BS; d <<= 1) {
        int t = (threadIdx.x >= d) ? s[threadIdx.x - d] : 0;
        __syncthreads();
        s[threadIdx.x] += t;
        __syncthreads();
    }
    if (gid < NN) g_off[gid] = s[threadIdx.x] - v;
    if (threadIdx.x == SCAN_BS - 1) g_bsum[blockIdx.x] = s[threadIdx.x];
}

// fixup: each block computes its own prefix over the 196 block sums
__global__ void k_scan2() {
    __shared__ int prefix;
    if (threadIdx.x == 0) {
        int acc = 0;
        for (int i = 0; i < blockIdx.x; i++) acc += g_bsum[i];
        prefix = acc;
    }
    __syncthreads();
    int gid = blockIdx.x * SCAN_BS + threadIdx.x;
    if (gid < NN) g_off[gid] += prefix;
    if (gid == 0) g_off[NN] = NE;
}

// place edges at CSR slots: plain 8B scattered stores, no atomics
__global__ void k_build(const float* __restrict__ ew) {
    int e = blockIdx.x * blockDim.x + threadIdx.x;
    if (e >= NE) return;
    int c = g_col32[e];
    int pos = g_off[c] + g_rank[e];
    g_packed[pos] = make_uint2((unsigned)g_row32[e], __float_as_uint(ew[e]));
}

// hs[node] = (x@W)*dinv ; dinv computed inline from CSR weights (deg = 1 + sum w)
__global__ void __launch_bounds__(256) k_gemm(const float* __restrict__ x,
                                              const float* __restrict__ W) {
    __shared__ float4 Ws[FIN * FOUT / 4];  // [k][f], 8KB
    for (int i = threadIdx.x; i < FIN * FOUT / 4; i += 256)
        Ws[i] = ((const float4*)W)[i];
    __syncthreads();

    int node = blockIdx.x * 256 + threadIdx.x;
    if (node >= NN) return;

    const float4* xr = (const float4*)(x + (size_t)node * FIN);
    float acc[FOUT];
#pragma unroll
    for (int f = 0; f < FOUT; f++) acc[f] = 0.0f;

#pragma unroll 4
    for (int k4 = 0; k4 < FIN / 4; k4++) {
        float4 xv = xr[k4];
#pragma unroll
        for (int j = 0; j < 4; j++) {
            float xs = (j == 0) ? xv.x : (j == 1) ? xv.y : (j == 2) ? xv.z : xv.w;
            int k = k4 * 4 + j;
#pragma unroll
            for (int q = 0; q < 4; q++) {
                float4 w = Ws[k * 4 + q];
                acc[q * 4 + 0] += xs * w.x;
                acc[q * 4 + 1] += xs * w.y;
                acc[q * 4 + 2] += xs * w.z;
                acc[q * 4 + 3] += xs * w.w;
            }
        }
    }

    // weighted degree from CSR segment (coalesced-ish streaming across threads)
    int beg = g_off[node], end = g_off[node + 1];
    float s = 1.0f;  // self-loop
    for (int p = beg; p < end; p++)
        s += __uint_as_float(g_packed[p].y);
    float di = rsqrtf(s);
    g_deg[node] = di;

    float4* hs4 = (float4*)(g_hs + (size_t)node * FOUT);
#pragma unroll
    for (int q = 0; q < 4; q++)
        hs4[q] = make_float4(acc[q * 4 + 0] * di, acc[q * 4 + 1] * di,
                             acc[q * 4 + 2] * di, acc[q * 4 + 3] * di);
}

// gather aggregation: 4 lanes per node (float4 each), 64 nodes per block, no atomics
__global__ void __launch_bounds__(256) k_agg(float* __restrict__ out,
                                             const float* __restrict__ b) {
    int tid = threadIdx.x;
    int lane4 = tid & 3;
    int node = blockIdx.x * 64 + (tid >> 2);
    if (node >= NN) return;

    int beg = g_off[node];
    int end = g_off[node + 1];
    float4 acc = make_float4(0.f, 0.f, 0.f, 0.f);

    int p = beg;
    for (; p + 2 <= end; p += 2) {   // 2-edge unroll for MLP
        uint2 pk0 = g_packed[p];
        uint2 pk1 = g_packed[p + 1];
        float4 h0 = ((const float4*)(g_hs + (size_t)pk0.x * FOUT))[lane4];
        float4 h1 = ((const float4*)(g_hs + (size_t)pk1.x * FOUT))[lane4];
        float w0 = __uint_as_float(pk0.y);
        float w1 = __uint_as_float(pk1.y);
        acc.x += w0 * h0.x + w1 * h1.x;
        acc.y += w0 * h0.y + w1 * h1.y;
        acc.z += w0 * h0.z + w1 * h1.z;
        acc.w += w0 * h0.w + w1 * h1.w;
    }
    if (p < end) {
        uint2 pk = g_packed[p];
        float w = __uint_as_float(pk.y);
        float4 h = ((const float4*)(g_hs + (size_t)pk.x * FOUT))[lane4];
        acc.x += w * h.x; acc.y += w * h.y; acc.z += w * h.z; acc.w += w * h.w;
    }

    float di = g_deg[node];
    float4 hself = ((const float4*)(g_hs + (size_t)node * FOUT))[lane4];
    float4 bv = ((const float4*)b)[lane4];
    float4 o;
    o.x = (acc.x + hself.x) * di + bv.x;
    o.y = (acc.y + hself.y) * di + bv.y;
    o.z = (acc.z + hself.z) * di + bv.z;
    o.w = (acc.w + hself.w) * di + bv.w;
    ((float4*)(out + (size_t)node * FOUT))[lane4] = o;
}

extern "C" void kernel_launch(void* const* d_in, const int* in_sizes, int n_in,
                              void* d_out, int out_size) {
    const float* x = (const float*)d_in[0];
    const void* ei = d_in[1];
    const float* ew = (const float*)d_in[2];
    const float* W = (const float*)d_in[3];
    const float* b = (const float*)d_in[4];
    float* out = (float*)d_out;

    k_init<<<(NN + 255) / 256, 256>>>((const unsigned int*)ei);
    k_pass1<<<(NE / 2 + 255) / 256, 256>>>(ei, ew);
    k_scan1<<<SCAN_NBLK, SCAN_BS>>>();
    k_scan2<<<SCAN_NBLK, SCAN_BS>>>();
    k_build<<<(NE + 255) / 256, 256>>>(ew);
    k_gemm<<<(NN + 255) / 256, 256>>>(x, W);
    k_agg<<<(NN + 63) / 64, 256>>>(out, b);
}